// round 15
// baseline (speedup 1.0000x reference)
#include <cuda_runtime.h>
#include <cuda_bf16.h>
#include <cstddef>
#include <cstdint>

// Problem constants
#define TT     1024
#define BBATCH 128
#define DD     128
#define HH     256
#define RTOT   (TT * BBATCH)   /* 131072 flat rows */
#define G4H    1024            /* 4*H gate columns */
#define SPAD   260             /* padded SMEM row stride (floats) */
#define BKC    64              /* GEMM K chunk in bf16 elements (128B rows) */

typedef unsigned long long ull;

// ---------------------------------------------------------------------------
// Scratch (static device globals -- no allocation APIs allowed)
// g_xg layout is PERMUTED for scan-side coalescing:
//   element (flat row r, gate col n) lives at ((n>>4)*RTOT + r)*16 + (n&15)
// ---------------------------------------------------------------------------
__device__ float g_xg[(size_t)RTOT * G4H];   // 512 MB gate staging (permuted)
__device__ float g_tmp[(size_t)RTOT * HH];   // 128 MB inter-layer activations
__device__ __align__(256) __nv_bfloat16 g_Ah[(size_t)RTOT * HH]; // 64 MB
__device__ __align__(256) __nv_bfloat16 g_Al[(size_t)RTOT * HH]; // 64 MB
__device__ __align__(256) __nv_bfloat16 g_Wh[1024 * HH];
__device__ __align__(256) __nv_bfloat16 g_Wl[1024 * HH];
// Per-row-group barrier state: [rg*64+0] = cnt, [rg*64+32] = gen (separate
// 128B lines). Sense-relative (base read per launch) + cnt self-resets =>
// deterministic across graph replays.
__device__ __align__(128) unsigned g_rgbar[16 * 64];

// ---------------------------------------------------------------------------
// Helpers (portable PTX only)
// ---------------------------------------------------------------------------
__device__ __forceinline__ void fma2(ull& d, ull a, ull b) {
    asm("fma.rn.f32x2 %0, %1, %2, %0;" : "+l"(d) : "l"(a), "l"(b));
}
__device__ __forceinline__ float2 unpack2(ull v) {
    unsigned lo, hi;
    asm("mov.b64 {%0, %1}, %2;" : "=r"(lo), "=r"(hi) : "l"(v));
    return make_float2(__uint_as_float(lo), __uint_as_float(hi));
}
__device__ __forceinline__ unsigned ld_acq(const unsigned* p) {
    unsigned v;
    asm volatile("ld.acquire.gpu.u32 %0, [%1];" : "=r"(v) : "l"(p) : "memory");
    return v;
}
__device__ __forceinline__ float sigf(float x) {
    return __fdividef(1.f, 1.f + __expf(-x));
}
__device__ __forceinline__ float tanh_fast(float x) {
    return 2.f * sigf(2.f * x) - 1.f;
}
__device__ __forceinline__ uint32_t smem_u32(const void* p) {
    uint32_t a;
    asm("{ .reg .u64 t; cvta.to.shared.u64 t, %1; cvt.u32.u64 %0, t; }"
        : "=r"(a) : "l"(p));
    return a;
}
#define SWZ(o) ((o) ^ (((o) >> 3) & 0x70))
__device__ __forceinline__ void cp16(uint32_t dst, const void* src) {
    asm volatile("cp.async.cg.shared.global [%0], [%1], 16;"
                 :: "r"(dst), "l"(src) : "memory");
}
__device__ __forceinline__ void ldm4(uint32_t* r, uint32_t addr) {
    asm volatile("ldmatrix.sync.aligned.m8n8.x4.shared.b16 {%0,%1,%2,%3}, [%4];"
                 : "=r"(r[0]), "=r"(r[1]), "=r"(r[2]), "=r"(r[3]) : "r"(addr));
}
__device__ __forceinline__ void mma_bf16(float* d, const uint32_t* a,
                                         const uint32_t* b) {
    asm volatile(
        "mma.sync.aligned.m16n8k16.row.col.f32.bf16.bf16.f32 "
        "{%0,%1,%2,%3}, {%4,%5,%6,%7}, {%8,%9}, {%0,%1,%2,%3};"
        : "+f"(d[0]), "+f"(d[1]), "+f"(d[2]), "+f"(d[3])
        : "r"(a[0]), "r"(a[1]), "r"(a[2]), "r"(a[3]), "r"(b[0]), "r"(b[1]));
}

// ---------------------------------------------------------------------------
// Split-conversion: fp32 -> (bf16 hi, bf16 lo). n4 = element count / 4.
// (network input x and weight matrices only; activation conversion is fused
//  into the scan's barrier-drain shadow)
// ---------------------------------------------------------------------------
__global__ void __launch_bounds__(256) convert_split_kernel(
    const float* __restrict__ src, __nv_bfloat16* __restrict__ hi,
    __nv_bfloat16* __restrict__ lo, int n4)
{
    int i = blockIdx.x * blockDim.x + threadIdx.x;
    if (i >= n4) return;
    float4 v = ((const float4*)src)[i];
    __nv_bfloat16 h0 = __float2bfloat16(v.x);
    __nv_bfloat16 h1 = __float2bfloat16(v.y);
    __nv_bfloat16 h2 = __float2bfloat16(v.z);
    __nv_bfloat16 h3 = __float2bfloat16(v.w);
    __nv_bfloat16 l0 = __float2bfloat16(v.x - __bfloat162float(h0));
    __nv_bfloat16 l1 = __float2bfloat16(v.y - __bfloat162float(h1));
    __nv_bfloat16 l2 = __float2bfloat16(v.z - __bfloat162float(h2));
    __nv_bfloat16 l3 = __float2bfloat16(v.w - __bfloat162float(h3));
    ((__nv_bfloat162*)hi)[2 * i]     = __nv_bfloat162(h0, h1);
    ((__nv_bfloat162*)hi)[2 * i + 1] = __nv_bfloat162(h2, h3);
    ((__nv_bfloat162*)lo)[2 * i]     = __nv_bfloat162(l0, l1);
    ((__nv_bfloat162*)lo)[2 * i + 1] = __nv_bfloat162(l2, l3);
}

// ---------------------------------------------------------------------------
// HMMA bf16-split GEMM (unchanged -- proven).
// xg[r][n] = sum_k A[r][k]*W[n][k] + bih[n]+bhh[n], output PERMUTED.
// ---------------------------------------------------------------------------
template <int K>
__global__ void __launch_bounds__(256) gemm_hmma_kernel(
    const float* __restrict__ bih, const float* __restrict__ bhh)
{
    extern __shared__ char smem[];
    const uint32_t abase = (smem_u32(smem) + 1023u) & ~1023u;

    const int tid  = threadIdx.x;
    const int wid  = tid >> 5;
    const int lane = tid & 31;
    const int col0 = blockIdx.x * 128;
    const int row0 = blockIdx.y * 128;
    const int wm   = wid & 1;
    const int wn   = wid >> 1;

    const __nv_bfloat16* Aop[3] = {g_Ah, g_Al, g_Ah};
    const __nv_bfloat16* Bop[3] = {g_Wh, g_Wh, g_Wl};
    constexpr int KCH = K / BKC;
    constexpr int NC  = 3 * KCH;

    auto prefetch = [&](int c) {
        const int pass = c / KCH;
        const int kc   = c % KCH;
        const __nv_bfloat16* A = Aop[pass];
        const __nv_bfloat16* B = Bop[pass];
        const uint32_t bufA = abase + (uint32_t)(c & 1) * 32768u;
        const uint32_t bufB = bufA + 16384u;
#pragma unroll
        for (int i = 0; i < 4; ++i) {
            int ch = tid + i * 256;
            int r  = ch >> 3;
            int cc = ch & 7;
            uint32_t off = SWZ((uint32_t)(r * 128 + cc * 16));
            cp16(bufA + off, A + (size_t)(row0 + r) * K + kc * BKC + cc * 8);
            cp16(bufB + off, B + (size_t)(col0 + r) * K + kc * BKC + cc * 8);
        }
        asm volatile("cp.async.commit_group;" ::: "memory");
    };

    float acc[4][4][4];
#pragma unroll
    for (int mt = 0; mt < 4; ++mt)
#pragma unroll
        for (int nt = 0; nt < 4; ++nt)
#pragma unroll
            for (int i = 0; i < 4; ++i) acc[mt][nt][i] = 0.f;

    prefetch(0);

    for (int c = 0; c < NC; ++c) {
        if (c + 1 < NC) {
            prefetch(c + 1);
            asm volatile("cp.async.wait_group 1;" ::: "memory");
        } else {
            asm volatile("cp.async.wait_group 0;" ::: "memory");
        }
        __syncthreads();

        const uint32_t bufA = abase + (uint32_t)(c & 1) * 32768u;
        const uint32_t bufB = bufA + 16384u;

#pragma unroll
        for (int ks = 0; ks < 4; ++ks) {
            uint32_t afr[4][4];
            {
                int arow = wm * 64 + (lane & 15);
                int kb   = ks * 32 + (lane >> 4) * 16;
#pragma unroll
                for (int mt = 0; mt < 4; ++mt)
                    ldm4(afr[mt],
                         bufA + SWZ((uint32_t)((arow + mt * 16) * 128 + kb)));
            }
            uint32_t bfr[4][2];
            {
                int j    = lane >> 3;
                int brow = (j >> 1) * 8 + (lane & 7);
                int kb   = ks * 32 + (j & 1) * 16;
#pragma unroll
                for (int p = 0; p < 2; ++p) {
                    uint32_t r[4];
                    ldm4(r, bufB +
                            SWZ((uint32_t)((wn * 32 + p * 16 + brow) * 128 + kb)));
                    bfr[p * 2][0]     = r[0];
                    bfr[p * 2][1]     = r[1];
                    bfr[p * 2 + 1][0] = r[2];
                    bfr[p * 2 + 1][1] = r[3];
                }
            }
#pragma unroll
            for (int mt = 0; mt < 4; ++mt)
#pragma unroll
                for (int nt = 0; nt < 4; ++nt)
                    mma_bf16(acc[mt][nt], afr[mt], bfr[nt]);
        }
        __syncthreads();
    }

#pragma unroll
    for (int nt = 0; nt < 4; ++nt) {
        int n0 = col0 + wn * 32 + nt * 8 + (lane & 3) * 2;
        float b0 = bih[n0] + bhh[n0];
        float b1 = bih[n0 + 1] + bhh[n0 + 1];
        size_t plane = (size_t)(n0 >> 4) * RTOT;
        int cc = n0 & 15;
#pragma unroll
        for (int mt = 0; mt < 4; ++mt) {
            int r0 = row0 + wm * 64 + mt * 16 + (lane >> 2);
            float2 v0 = make_float2(acc[mt][nt][0] + b0, acc[mt][nt][1] + b1);
            float2 v1 = make_float2(acc[mt][nt][2] + b0, acc[mt][nt][3] + b1);
            *(float2*)&g_xg[(plane + r0) * 16 + cc]     = v0;
            *(float2*)&g_xg[(plane + r0 + 8) * 16 + cc] = v1;
        }
    }
}

// ---------------------------------------------------------------------------
// Persistent recurrent scan: EXACT R6 structure (measured best, 6.06us/step)
// with ONE delta: when BF16OUT, the bf16 hi/lo activation split for the next
// layer's GEMM is written in the barrier-drain SHADOW (after the flag
// release), so it never touches the inter-block critical path. Safety: Ssm
// is next overwritten only after the next iteration's post-stage
// __syncthreads, which all threads must reach after finishing shadow work.
// Block (cg, rg): cg = bid % NCG owns CW h-columns, rg = bid / NCG owns RW
// contiguous rows. Per-rg counting barrier, sense-relative.
// ---------------------------------------------------------------------------
template <int MB, int CW, int RPT, bool BF16OUT>
__global__ void __launch_bounds__(256, 1) scan_kernel(
    const float* __restrict__ Whh,   // [1024, 256] row-major
    float* __restrict__ out,         // [nsteps*MB, 256]
    int nsteps)
{
    constexpr int RPW = 256 / CW;        // row slots per column
    constexpr int RW  = RPW * RPT;       // rows per block
    constexpr int NCG = 256 / CW;        // column groups = barrier group size
    constexpr int CWP = (CW == 16) ? 18 : 36;  // conflict-free padded stride
    constexpr int NSL = CW / 16;         // 16-col planes per block

    extern __shared__ float smemf[];
    float* Wsm = smemf;                          // [4*CW][SPAD]
    float* Hsm = Wsm + 4 * CW * SPAD;            // [RW][SPAD]
    float* Xsm = Hsm + RW * SPAD;                // [2][4][RW][CWP]
    float* Ssm = Xsm + 2 * 4 * RW * CWP;         // [RW][CWP]

    const int tid     = threadIdx.x;
    const int cg      = blockIdx.x % NCG;
    const int rg      = blockIdx.x / NCG;
    const int gc0     = cg * CW;
    const int rowbase = rg * RW;
    const int c       = tid / RPW;       // owned column (0..CW-1)
    const int q       = tid % RPW;       // row slot

    unsigned* bcnt = &g_rgbar[rg * 64];
    unsigned* bgen = &g_rgbar[rg * 64 + 32];
    // Safe: this rg's gen cannot advance until THIS block arrives.
    const unsigned gbase = ld_acq(bgen);

    for (int idx = tid; idx < 4 * CW * 64; idx += 256) {
        int k4 = idx % 64;
        int cc = (idx / 64) % CW;
        int g  = idx / (64 * CW);
        float4 v = *(const float4*)&Whh[(size_t)(g * 256 + gc0 + cc) * HH + k4 * 4];
        *(float4*)&Wsm[(g * CW + cc) * SPAD + k4 * 4] = v;
    }

    // Pre-stage step-0 seeds into Xsm[0]
    for (int idx = tid; idx < 4 * NSL * RW * 4; idx += 256) {
        int c4   = idx & 3;
        int r    = (idx >> 2) % RW;
        int rest = idx / (4 * RW);
        int cgi  = rest % NSL;
        int g    = rest / NSL;
        const float* src =
            &g_xg[((size_t)(g * 16 + cg * NSL + cgi) * RTOT + rowbase + r) * 16
                  + c4 * 4];
        float4 v = *(const float4*)src;
        float* dst = &Xsm[(g * RW + r) * CWP + cgi * 16 + c4 * 4];
        dst[0] = v.x; dst[1] = v.y; dst[2] = v.z; dst[3] = v.w;
    }

    float c_st[RPT];
#pragma unroll
    for (int j = 0; j < RPT; ++j) c_st[j] = 0.f;

    for (int step = 0; step < nsteps; ++step) {
        const int buf = step & 1;

        if (step > 0) {
            // All threads poll the row-group generation (broadcast load).
            const unsigned target = gbase + (unsigned)step;
            while ((int)(ld_acq(bgen) - target) < 0) { }
            // Stage h_prev slab (coalesced float4)
            const float* hp = out + ((size_t)(step - 1) * MB + rowbase) * HH;
            for (int idx = tid; idx < RW * 64; idx += 256) {
                int r  = idx / 64;
                int k4 = idx % 64;
                float4 v = *(const float4*)&hp[r * HH + k4 * 4];
                *(float4*)&Hsm[r * SPAD + k4 * 4] = v;
            }
        }
        __syncthreads();   // Hsm + Xsm[buf] ready

        const float* Xb = Xsm + buf * 4 * RW * CWP;
        ull acc[RPT][4];
#pragma unroll
        for (int j = 0; j < RPT; ++j)
#pragma unroll
            for (int g = 0; g < 4; ++g)
                acc[j][g] =
                    (ull)__float_as_uint(Xb[(g * RW + q + j * RPW) * CWP + c]);

        if (step > 0) {
#pragma unroll 2
            for (int k4 = 0; k4 < 64; ++k4) {
                ulonglong2 w[4];
#pragma unroll
                for (int g = 0; g < 4; ++g)
                    w[g] = *(const ulonglong2*)&Wsm[(g * CW + c) * SPAD + k4 * 4];
#pragma unroll
                for (int j = 0; j < RPT; ++j) {
                    ulonglong2 h2 =
                        *(const ulonglong2*)&Hsm[(q + j * RPW) * SPAD + k4 * 4];
#pragma unroll
                    for (int g = 0; g < 4; ++g) {
                        fma2(acc[j][g], h2.x, w[g].x);
                        fma2(acc[j][g], h2.y, w[g].y);
                    }
                }
            }
        }

        // LSTM cell -> stage h into Ssm
#pragma unroll
        for (int j = 0; j < RPT; ++j) {
            float2 pi = unpack2(acc[j][0]);
            float2 pf = unpack2(acc[j][1]);
            float2 pg = unpack2(acc[j][2]);
            float2 po = unpack2(acc[j][3]);
            float vi = pi.x + pi.y;
            float vf = pf.x + pf.y;
            float vg = pg.x + pg.y;
            float vo = po.x + po.y;
            float ig = sigf(vi);
            float fg = sigf(vf);
            float gt = tanh_fast(vg);
            float og = sigf(vo);
            float cc2 = fg * c_st[j] + ig * gt;
            c_st[j] = cc2;
            Ssm[(q + j * RPW) * CWP + c] = og * tanh_fast(cc2);
        }
        __syncthreads();   // Ssm ready; Hsm/Xsm[buf] reads done

        // Coalesced fp32 h store (exchange medium + layer output)
        const size_t rowflat = (size_t)step * MB + rowbase;
        {
            float* orow = out + rowflat * HH + gc0;
            for (int idx = tid; idx < RW * (CW / 4); idx += 256) {
                int c4 = idx % (CW / 4);
                int r  = idx / (CW / 4);
                const float* s = &Ssm[r * CWP + c4 * 4];
                float4 v = make_float4(s[0], s[1], s[2], s[3]);
                *(float4*)&orow[(size_t)r * HH + c4 * 4] = v;
            }
        }
        __syncthreads();   // all h stores issued, block-visible

        if (step + 1 < nsteps) {
            // Release-arrive on the row-group barrier (thread 0) FIRST --
            // everything below runs in the barrier-drain shadow.
            if (tid == 0) {
                __threadfence();
                if (atomicAdd(bcnt, 1u) == (unsigned)(NCG - 1)) {
                    atomicExch(bcnt, 0u);
                    __threadfence();
                    atomicAdd(bgen, 1u);
                }
            }
            // SHADOW 1: bf16 hi/lo split for the next layer's GEMM operand.
            if (BF16OUT) {
                for (int idx = tid; idx < RW * (CW / 4); idx += 256) {
                    int c4 = idx % (CW / 4);
                    int r  = idx / (CW / 4);
                    const float* s = &Ssm[r * CWP + c4 * 4];
                    float4 v = make_float4(s[0], s[1], s[2], s[3]);
                    __nv_bfloat16 h0 = __float2bfloat16(v.x);
                    __nv_bfloat16 h1 = __float2bfloat16(v.y);
                    __nv_bfloat16 h2 = __float2bfloat16(v.z);
                    __nv_bfloat16 h3 = __float2bfloat16(v.w);
                    __nv_bfloat16 l0 = __float2bfloat16(v.x - __bfloat162float(h0));
                    __nv_bfloat16 l1 = __float2bfloat16(v.y - __bfloat162float(h1));
                    __nv_bfloat16 l2 = __float2bfloat16(v.z - __bfloat162float(h2));
                    __nv_bfloat16 l3 = __float2bfloat16(v.w - __bfloat162float(h3));
                    size_t ab = (rowflat + r) * HH + gc0 + c4 * 4;
                    *(__nv_bfloat162*)&g_Ah[ab]     = __nv_bfloat162(h0, h1);
                    *(__nv_bfloat162*)&g_Ah[ab + 2] = __nv_bfloat162(h2, h3);
                    *(__nv_bfloat162*)&g_Al[ab]     = __nv_bfloat162(l0, l1);
                    *(__nv_bfloat162*)&g_Al[ab + 2] = __nv_bfloat162(l2, l3);
                }
            }
            // SHADOW 2: prefetch next step's seeds into the alternate buffer.
            const size_t srow0 = (size_t)(step + 1) * MB + rowbase;
            float* Xn = Xsm + (1 - buf) * 4 * RW * CWP;
            for (int idx = tid; idx < 4 * NSL * RW * 4; idx += 256) {
                int c4   = idx & 3;
                int r    = (idx >> 2) % RW;
                int rest = idx / (4 * RW);
                int cgi  = rest % NSL;
                int g    = rest / NSL;
                const float* src =
                    &g_xg[((size_t)(g * 16 + cg * NSL + cgi) * RTOT + srow0 + r) * 16
                          + c4 * 4];
                float4 v = *(const float4*)src;
                float* dst = &Xn[(g * RW + r) * CWP + cgi * 16 + c4 * 4];
                dst[0] = v.x; dst[1] = v.y; dst[2] = v.z; dst[3] = v.w;
            }
        } else if (BF16OUT) {
            // Final step: still must emit bf16 for the next layer's GEMM.
            for (int idx = tid; idx < RW * (CW / 4); idx += 256) {
                int c4 = idx % (CW / 4);
                int r  = idx / (CW / 4);
                const float* s = &Ssm[r * CWP + c4 * 4];
                float4 v = make_float4(s[0], s[1], s[2], s[3]);
                __nv_bfloat16 h0 = __float2bfloat16(v.x);
                __nv_bfloat16 h1 = __float2bfloat16(v.y);
                __nv_bfloat16 h2 = __float2bfloat16(v.z);
                __nv_bfloat16 h3 = __float2bfloat16(v.w);
                __nv_bfloat16 l0 = __float2bfloat16(v.x - __bfloat162float(h0));
                __nv_bfloat16 l1 = __float2bfloat16(v.y - __bfloat162float(h1));
                __nv_bfloat16 l2 = __float2bfloat16(v.z - __bfloat162float(h2));
                __nv_bfloat16 l3 = __float2bfloat16(v.w - __bfloat162float(h3));
                size_t ab = (rowflat + r) * HH + gc0 + c4 * 4;
                *(__nv_bfloat162*)&g_Ah[ab]     = __nv_bfloat162(h0, h1);
                *(__nv_bfloat162*)&g_Ah[ab + 2] = __nv_bfloat162(h2, h3);
                *(__nv_bfloat162*)&g_Al[ab]     = __nv_bfloat162(l0, l1);
                *(__nv_bfloat162*)&g_Al[ab + 2] = __nv_bfloat162(l2, l3);
            }
        }
    }
}

// ---------------------------------------------------------------------------
// kernel_launch: per layer: (weight convert) -> HMMA GEMM -> scan (which
// itself emits the next layer's bf16 operands in its barrier shadow).
// Graph-capturable, allocation-free, deterministic.
// ---------------------------------------------------------------------------
extern "C" void kernel_launch(void* const* d_in, const int* in_sizes, int n_in,
                              void* d_out, int out_size)
{
    (void)in_sizes; (void)n_in; (void)out_size;
    const float* x    = (const float*)d_in[0];
    const float* Wih0 = (const float*)d_in[1];
    const float* Whh0 = (const float*)d_in[2];
    const float* bih0 = (const float*)d_in[3];
    const float* bhh0 = (const float*)d_in[4];
    const float* Wih1 = (const float*)d_in[5];
    const float* Whh1 = (const float*)d_in[6];
    const float* bih1 = (const float*)d_in[7];
    const float* bhh1 = (const float*)d_in[8];
    const float* Wih2 = (const float*)d_in[9];
    const float* Whh2 = (const float*)d_in[10];
    const float* bih2 = (const float*)d_in[11];
    const float* bhh2 = (const float*)d_in[12];
    float* out = (float*)d_out;

    float* tmp = nullptr;
    cudaGetSymbolAddress((void**)&tmp, g_tmp);
    __nv_bfloat16 *Ah = nullptr, *Al = nullptr, *Wh = nullptr, *Wl = nullptr;
    cudaGetSymbolAddress((void**)&Ah, g_Ah);
    cudaGetSymbolAddress((void**)&Al, g_Al);
    cudaGetSymbolAddress((void**)&Wh, g_Wh);
    cudaGetSymbolAddress((void**)&Wl, g_Wl);

    // Scan SMEM: (4*CW + RW)*SPAD + 9*RW*CWP floats
    const int smem0 = ((4 * 16 + 16) * SPAD + 9 * 16 * 18) * 4;   //  93952 B
    const int smem1 = ((4 * 32 + 16) * SPAD + 9 * 16 * 36) * 4;   // 170496 B
    const int smem2 = ((4 * 32 + 32) * SPAD + 9 * 32 * 36) * 4;   // 207872 B
    cudaFuncSetAttribute((const void*)scan_kernel<128, 16, 1, true>,
                         cudaFuncAttributeMaxDynamicSharedMemorySize, smem0);
    cudaFuncSetAttribute((const void*)scan_kernel<256, 32, 2, true>,
                         cudaFuncAttributeMaxDynamicSharedMemorySize, smem1);
    cudaFuncSetAttribute((const void*)scan_kernel<512, 32, 4, false>,
                         cudaFuncAttributeMaxDynamicSharedMemorySize, smem2);

    const int gsm = 1024 + 2 * 32768;
    cudaFuncSetAttribute((const void*)gemm_hmma_kernel<128>,
                         cudaFuncAttributeMaxDynamicSharedMemorySize, gsm);
    cudaFuncSetAttribute((const void*)gemm_hmma_kernel<256>,
                         cudaFuncAttributeMaxDynamicSharedMemorySize, gsm);

    dim3 ggrid(8, 1024);   // 128-col x 128-row tiles over [131072 x 1024]

    // ---- Layer 0: K=128, MB=128, 1024 steps
    {
        int n4a = RTOT * 128 / 4;
        convert_split_kernel<<<(n4a + 255) / 256, 256>>>(x, Ah, Al, n4a);
        int n4w = 1024 * 128 / 4;
        convert_split_kernel<<<(n4w + 255) / 256, 256>>>(Wih0, Wh, Wl, n4w);
        gemm_hmma_kernel<128><<<ggrid, 256, gsm>>>(bih0, bhh0);
        scan_kernel<128, 16, 1, true><<<128, 256, smem0>>>(Whh0, tmp, 1024);
    }
    // ---- Layer 1: K=256, MB=256, 512 steps (A bf16 produced by scan 0)
    {
        int n4w = 1024 * 256 / 4;
        convert_split_kernel<<<(n4w + 255) / 256, 256>>>(Wih1, Wh, Wl, n4w);
        gemm_hmma_kernel<256><<<ggrid, 256, gsm>>>(bih1, bhh1);
        scan_kernel<256, 32, 2, true><<<128, 256, smem1>>>(Whh1, tmp, 512);
    }
    // ---- Layer 2: K=256, MB=512, 256 steps (A bf16 produced by scan 1)
    {
        int n4w = 1024 * 256 / 4;
        convert_split_kernel<<<(n4w + 255) / 256, 256>>>(Wih2, Wh, Wl, n4w);
        gemm_hmma_kernel<256><<<ggrid, 256, gsm>>>(bih2, bhh2);
        scan_kernel<512, 32, 4, false><<<128, 256, smem2>>>(Whh2, out, 256);
    }
}

// round 17
// speedup vs baseline: 1.0674x; 1.0674x over previous
#include <cuda_runtime.h>
#include <cuda_bf16.h>
#include <cstddef>
#include <cstdint>

// Problem constants
#define TT     1024
#define BBATCH 128
#define DD     128
#define HH     256
#define RTOT   (TT * BBATCH)   /* 131072 flat rows */
#define G4H    1024            /* 4*H gate columns */
#define SPAD   260             /* padded SMEM row stride (floats) */
#define BKC    64              /* GEMM K chunk in bf16 elements (128B rows) */

typedef unsigned long long ull;

// ---------------------------------------------------------------------------
// Scratch (static device globals -- no allocation APIs allowed)
// g_xg layout is PERMUTED for scan-side coalescing:
//   element (flat row r, gate col n) lives at ((n>>4)*RTOT + r)*16 + (n&15)
// ---------------------------------------------------------------------------
__device__ float g_xg[(size_t)RTOT * G4H];   // 512 MB gate staging (permuted)
__device__ float g_tmp[(size_t)RTOT * HH];   // 128 MB inter-layer activations
__device__ __align__(256) __nv_bfloat16 g_Ah[(size_t)RTOT * HH]; // 64 MB
__device__ __align__(256) __nv_bfloat16 g_Al[(size_t)RTOT * HH]; // 64 MB
__device__ __align__(256) __nv_bfloat16 g_Wh[1024 * HH];
__device__ __align__(256) __nv_bfloat16 g_Wl[1024 * HH];
// Per-row-group barrier state: [rg*64+0] = cnt, [rg*64+32] = gen (separate
// 128B lines). Sense-relative (base read per launch) + cnt self-resets =>
// deterministic across graph replays.
__device__ __align__(128) unsigned g_rgbar[16 * 64];

// ---------------------------------------------------------------------------
// Helpers (portable PTX only)
// ---------------------------------------------------------------------------
__device__ __forceinline__ void fma2(ull& d, ull a, ull b) {
    asm("fma.rn.f32x2 %0, %1, %2, %0;" : "+l"(d) : "l"(a), "l"(b));
}
__device__ __forceinline__ float2 unpack2(ull v) {
    unsigned lo, hi;
    asm("mov.b64 {%0, %1}, %2;" : "=r"(lo), "=r"(hi) : "l"(v));
    return make_float2(__uint_as_float(lo), __uint_as_float(hi));
}
__device__ __forceinline__ unsigned ld_acq(const unsigned* p) {
    unsigned v;
    asm volatile("ld.acquire.gpu.u32 %0, [%1];" : "=r"(v) : "l"(p) : "memory");
    return v;
}
__device__ __forceinline__ float sigf(float x) {
    return __fdividef(1.f, 1.f + __expf(-x));
}
__device__ __forceinline__ float tanh_fast(float x) {
    return 2.f * sigf(2.f * x) - 1.f;
}
__device__ __forceinline__ uint32_t smem_u32(const void* p) {
    uint32_t a;
    asm("{ .reg .u64 t; cvta.to.shared.u64 t, %1; cvt.u32.u64 %0, t; }"
        : "=r"(a) : "l"(p));
    return a;
}
#define SWZ(o) ((o) ^ (((o) >> 3) & 0x70))
__device__ __forceinline__ void cp16(uint32_t dst, const void* src) {
    asm volatile("cp.async.cg.shared.global [%0], [%1], 16;"
                 :: "r"(dst), "l"(src) : "memory");
}
__device__ __forceinline__ void ldm4(uint32_t* r, uint32_t addr) {
    asm volatile("ldmatrix.sync.aligned.m8n8.x4.shared.b16 {%0,%1,%2,%3}, [%4];"
                 : "=r"(r[0]), "=r"(r[1]), "=r"(r[2]), "=r"(r[3]) : "r"(addr));
}
__device__ __forceinline__ void mma_bf16(float* d, const uint32_t* a,
                                         const uint32_t* b) {
    asm volatile(
        "mma.sync.aligned.m16n8k16.row.col.f32.bf16.bf16.f32 "
        "{%0,%1,%2,%3}, {%4,%5,%6,%7}, {%8,%9}, {%0,%1,%2,%3};"
        : "+f"(d[0]), "+f"(d[1]), "+f"(d[2]), "+f"(d[3])
        : "r"(a[0]), "r"(a[1]), "r"(a[2]), "r"(a[3]), "r"(b[0]), "r"(b[1]));
}

// ---------------------------------------------------------------------------
// Split-conversion: fp32 -> (bf16 hi, bf16 lo). n4 = element count / 4.
// ---------------------------------------------------------------------------
__global__ void __launch_bounds__(256) convert_split_kernel(
    const float* __restrict__ src, __nv_bfloat16* __restrict__ hi,
    __nv_bfloat16* __restrict__ lo, int n4)
{
    int i = blockIdx.x * blockDim.x + threadIdx.x;
    if (i >= n4) return;
    float4 v = ((const float4*)src)[i];
    __nv_bfloat16 h0 = __float2bfloat16(v.x);
    __nv_bfloat16 h1 = __float2bfloat16(v.y);
    __nv_bfloat16 h2 = __float2bfloat16(v.z);
    __nv_bfloat16 h3 = __float2bfloat16(v.w);
    __nv_bfloat16 l0 = __float2bfloat16(v.x - __bfloat162float(h0));
    __nv_bfloat16 l1 = __float2bfloat16(v.y - __bfloat162float(h1));
    __nv_bfloat16 l2 = __float2bfloat16(v.z - __bfloat162float(h2));
    __nv_bfloat16 l3 = __float2bfloat16(v.w - __bfloat162float(h3));
    ((__nv_bfloat162*)hi)[2 * i]     = __nv_bfloat162(h0, h1);
    ((__nv_bfloat162*)hi)[2 * i + 1] = __nv_bfloat162(h2, h3);
    ((__nv_bfloat162*)lo)[2 * i]     = __nv_bfloat162(l0, l1);
    ((__nv_bfloat162*)lo)[2 * i + 1] = __nv_bfloat162(l2, l3);
}

// ---------------------------------------------------------------------------
// HMMA bf16-split GEMM, TWO passes: (Ah,Wh) + (Al,Wh).
// The dropped Ah*Wl term contributes ~2^-9 relative weight error ->
// ~1e-4 xg relative error (threshold 1e-3; measured headroom 1.8e-6).
// xg[r][n] = sum_k A[r][k]*W[n][k] + bih[n]+bhh[n], output PERMUTED.
// ---------------------------------------------------------------------------
template <int K>
__global__ void __launch_bounds__(256) gemm_hmma_kernel(
    const float* __restrict__ bih, const float* __restrict__ bhh)
{
    extern __shared__ char smem[];
    const uint32_t abase = (smem_u32(smem) + 1023u) & ~1023u;

    const int tid  = threadIdx.x;
    const int wid  = tid >> 5;
    const int lane = tid & 31;
    const int col0 = blockIdx.x * 128;
    const int row0 = blockIdx.y * 128;
    const int wm   = wid & 1;
    const int wn   = wid >> 1;

    const __nv_bfloat16* Aop[2] = {g_Ah, g_Al};
    constexpr int KCH = K / BKC;
    constexpr int NC  = 2 * KCH;

    auto prefetch = [&](int c) {
        const int pass = c / KCH;
        const int kc   = c % KCH;
        const __nv_bfloat16* A = Aop[pass];
        const __nv_bfloat16* B = g_Wh;
        const uint32_t bufA = abase + (uint32_t)(c & 1) * 32768u;
        const uint32_t bufB = bufA + 16384u;
#pragma unroll
        for (int i = 0; i < 4; ++i) {
            int ch = tid + i * 256;
            int r  = ch >> 3;
            int cc = ch & 7;
            uint32_t off = SWZ((uint32_t)(r * 128 + cc * 16));
            cp16(bufA + off, A + (size_t)(row0 + r) * K + kc * BKC + cc * 8);
            cp16(bufB + off, B + (size_t)(col0 + r) * K + kc * BKC + cc * 8);
        }
        asm volatile("cp.async.commit_group;" ::: "memory");
    };

    float acc[4][4][4];
#pragma unroll
    for (int mt = 0; mt < 4; ++mt)
#pragma unroll
        for (int nt = 0; nt < 4; ++nt)
#pragma unroll
            for (int i = 0; i < 4; ++i) acc[mt][nt][i] = 0.f;

    prefetch(0);

    for (int c = 0; c < NC; ++c) {
        if (c + 1 < NC) {
            prefetch(c + 1);
            asm volatile("cp.async.wait_group 1;" ::: "memory");
        } else {
            asm volatile("cp.async.wait_group 0;" ::: "memory");
        }
        __syncthreads();

        const uint32_t bufA = abase + (uint32_t)(c & 1) * 32768u;
        const uint32_t bufB = bufA + 16384u;

#pragma unroll
        for (int ks = 0; ks < 4; ++ks) {
            uint32_t afr[4][4];
            {
                int arow = wm * 64 + (lane & 15);
                int kb   = ks * 32 + (lane >> 4) * 16;
#pragma unroll
                for (int mt = 0; mt < 4; ++mt)
                    ldm4(afr[mt],
                         bufA + SWZ((uint32_t)((arow + mt * 16) * 128 + kb)));
            }
            uint32_t bfr[4][2];
            {
                int j    = lane >> 3;
                int brow = (j >> 1) * 8 + (lane & 7);
                int kb   = ks * 32 + (j & 1) * 16;
#pragma unroll
                for (int p = 0; p < 2; ++p) {
                    uint32_t r[4];
                    ldm4(r, bufB +
                            SWZ((uint32_t)((wn * 32 + p * 16 + brow) * 128 + kb)));
                    bfr[p * 2][0]     = r[0];
                    bfr[p * 2][1]     = r[1];
                    bfr[p * 2 + 1][0] = r[2];
                    bfr[p * 2 + 1][1] = r[3];
                }
            }
#pragma unroll
            for (int mt = 0; mt < 4; ++mt)
#pragma unroll
                for (int nt = 0; nt < 4; ++nt)
                    mma_bf16(acc[mt][nt], afr[mt], bfr[nt]);
        }
        __syncthreads();
    }

#pragma unroll
    for (int nt = 0; nt < 4; ++nt) {
        int n0 = col0 + wn * 32 + nt * 8 + (lane & 3) * 2;
        float b0 = bih[n0] + bhh[n0];
        float b1 = bih[n0 + 1] + bhh[n0 + 1];
        size_t plane = (size_t)(n0 >> 4) * RTOT;
        int cc = n0 & 15;
#pragma unroll
        for (int mt = 0; mt < 4; ++mt) {
            int r0 = row0 + wm * 64 + mt * 16 + (lane >> 2);
            float2 v0 = make_float2(acc[mt][nt][0] + b0, acc[mt][nt][1] + b1);
            float2 v1 = make_float2(acc[mt][nt][2] + b0, acc[mt][nt][3] + b1);
            *(float2*)&g_xg[(plane + r0) * 16 + cc]     = v0;
            *(float2*)&g_xg[(plane + r0 + 8) * 16 + cc] = v1;
        }
    }
}

// ---------------------------------------------------------------------------
// Persistent recurrent scan -- BYTE-EXACT R6 structure (measured best,
// 6.06 us/step). Per-row-group counting barrier, all-thread poll, seed
// double-buffer prefetched in the barrier shadow.
// Block (cg, rg): cg = bid % NCG owns CW h-columns, rg = bid / NCG owns RW
// contiguous rows.
// ---------------------------------------------------------------------------
template <int MB, int CW, int RPT>
__global__ void __launch_bounds__(256, 1) scan_kernel(
    const float* __restrict__ Whh,   // [1024, 256] row-major
    float* __restrict__ out,         // [nsteps*MB, 256]
    int nsteps)
{
    constexpr int RPW = 256 / CW;        // row slots per column
    constexpr int RW  = RPW * RPT;       // rows per block
    constexpr int NCG = 256 / CW;        // column groups = barrier group size
    constexpr int CWP = (CW == 16) ? 18 : 36;  // conflict-free padded stride
    constexpr int NSL = CW / 16;         // 16-col planes per block

    extern __shared__ float smemf[];
    float* Wsm = smemf;                          // [4*CW][SPAD]
    float* Hsm = Wsm + 4 * CW * SPAD;            // [RW][SPAD]
    float* Xsm = Hsm + RW * SPAD;                // [2][4][RW][CWP]
    float* Ssm = Xsm + 2 * 4 * RW * CWP;         // [RW][CWP]

    const int tid     = threadIdx.x;
    const int cg      = blockIdx.x % NCG;
    const int rg      = blockIdx.x / NCG;
    const int gc0     = cg * CW;
    const int rowbase = rg * RW;
    const int c       = tid / RPW;       // owned column (0..CW-1)
    const int q       = tid % RPW;       // row slot

    unsigned* bcnt = &g_rgbar[rg * 64];
    unsigned* bgen = &g_rgbar[rg * 64 + 32];
    // Safe: this rg's gen cannot advance until THIS block arrives.
    const unsigned gbase = ld_acq(bgen);

    for (int idx = tid; idx < 4 * CW * 64; idx += 256) {
        int k4 = idx % 64;
        int cc = (idx / 64) % CW;
        int g  = idx / (64 * CW);
        float4 v = *(const float4*)&Whh[(size_t)(g * 256 + gc0 + cc) * HH + k4 * 4];
        *(float4*)&Wsm[(g * CW + cc) * SPAD + k4 * 4] = v;
    }

    // Pre-stage step-0 seeds into Xsm[0]
    for (int idx = tid; idx < 4 * NSL * RW * 4; idx += 256) {
        int c4   = idx & 3;
        int r    = (idx >> 2) % RW;
        int rest = idx / (4 * RW);
        int cgi  = rest % NSL;
        int g    = rest / NSL;
        const float* src =
            &g_xg[((size_t)(g * 16 + cg * NSL + cgi) * RTOT + rowbase + r) * 16
                  + c4 * 4];
        float4 v = *(const float4*)src;
        float* dst = &Xsm[(g * RW + r) * CWP + cgi * 16 + c4 * 4];
        dst[0] = v.x; dst[1] = v.y; dst[2] = v.z; dst[3] = v.w;
    }

    float c_st[RPT];
#pragma unroll
    for (int j = 0; j < RPT; ++j) c_st[j] = 0.f;

    for (int step = 0; step < nsteps; ++step) {
        const int buf = step & 1;

        if (step > 0) {
            // All threads poll the row-group generation (broadcast load).
            const unsigned target = gbase + (unsigned)step;
            while ((int)(ld_acq(bgen) - target) < 0) { }
            // Stage h_prev slab (coalesced float4)
            const float* hp = out + ((size_t)(step - 1) * MB + rowbase) * HH;
            for (int idx = tid; idx < RW * 64; idx += 256) {
                int r  = idx / 64;
                int k4 = idx % 64;
                float4 v = *(const float4*)&hp[r * HH + k4 * 4];
                *(float4*)&Hsm[r * SPAD + k4 * 4] = v;
            }
        }
        __syncthreads();   // Hsm + Xsm[buf] ready

        const float* Xb = Xsm + buf * 4 * RW * CWP;
        ull acc[RPT][4];
#pragma unroll
        for (int j = 0; j < RPT; ++j)
#pragma unroll
            for (int g = 0; g < 4; ++g)
                acc[j][g] =
                    (ull)__float_as_uint(Xb[(g * RW + q + j * RPW) * CWP + c]);

        if (step > 0) {
#pragma unroll 2
            for (int k4 = 0; k4 < 64; ++k4) {
                ulonglong2 w[4];
#pragma unroll
                for (int g = 0; g < 4; ++g)
                    w[g] = *(const ulonglong2*)&Wsm[(g * CW + c) * SPAD + k4 * 4];
#pragma unroll
                for (int j = 0; j < RPT; ++j) {
                    ulonglong2 h2 =
                        *(const ulonglong2*)&Hsm[(q + j * RPW) * SPAD + k4 * 4];
#pragma unroll
                    for (int g = 0; g < 4; ++g) {
                        fma2(acc[j][g], h2.x, w[g].x);
                        fma2(acc[j][g], h2.y, w[g].y);
                    }
                }
            }
        }

        // LSTM cell -> stage h into Ssm
#pragma unroll
        for (int j = 0; j < RPT; ++j) {
            float2 pi = unpack2(acc[j][0]);
            float2 pf = unpack2(acc[j][1]);
            float2 pg = unpack2(acc[j][2]);
            float2 po = unpack2(acc[j][3]);
            float vi = pi.x + pi.y;
            float vf = pf.x + pf.y;
            float vg = pg.x + pg.y;
            float vo = po.x + po.y;
            float ig = sigf(vi);
            float fg = sigf(vf);
            float gt = tanh_fast(vg);
            float og = sigf(vo);
            float cc2 = fg * c_st[j] + ig * gt;
            c_st[j] = cc2;
            Ssm[(q + j * RPW) * CWP + c] = og * tanh_fast(cc2);
        }
        __syncthreads();   // Ssm ready; Hsm/Xsm[buf] reads done

        // Coalesced h store
        {
            float* orow = out + ((size_t)step * MB + rowbase) * HH + gc0;
            for (int idx = tid; idx < RW * (CW / 4); idx += 256) {
                int c4 = idx % (CW / 4);
                int r  = idx / (CW / 4);
                const float* s = &Ssm[r * CWP + c4 * 4];
                float4 v = make_float4(s[0], s[1], s[2], s[3]);
                *(float4*)&orow[(size_t)r * HH + c4 * 4] = v;
            }
        }
        __syncthreads();   // all h stores issued, block-visible

        if (step + 1 < nsteps) {
            // Release-arrive on the row-group barrier (thread 0)
            if (tid == 0) {
                __threadfence();
                if (atomicAdd(bcnt, 1u) == (unsigned)(NCG - 1)) {
                    atomicExch(bcnt, 0u);
                    __threadfence();
                    atomicAdd(bgen, 1u);
                }
            }
            // Prefetch next step's seeds into the alternate buffer while the
            // row-group barrier drains (off the critical path).
            const size_t srow0 = (size_t)(step + 1) * MB + rowbase;
            float* Xn = Xsm + (1 - buf) * 4 * RW * CWP;
            for (int idx = tid; idx < 4 * NSL * RW * 4; idx += 256) {
                int c4   = idx & 3;
                int r    = (idx >> 2) % RW;
                int rest = idx / (4 * RW);
                int cgi  = rest % NSL;
                int g    = rest / NSL;
                const float* src =
                    &g_xg[((size_t)(g * 16 + cg * NSL + cgi) * RTOT + srow0 + r) * 16
                          + c4 * 4];
                float4 v = *(const float4*)src;
                float* dst = &Xn[(g * RW + r) * CWP + cgi * 16 + c4 * 4];
                dst[0] = v.x; dst[1] = v.y; dst[2] = v.z; dst[3] = v.w;
            }
        }
    }
}

// ---------------------------------------------------------------------------
// kernel_launch: per layer: split-convert A & W -> 2-pass HMMA GEMM -> scan.
// Graph-capturable, allocation-free, deterministic.
// ---------------------------------------------------------------------------
extern "C" void kernel_launch(void* const* d_in, const int* in_sizes, int n_in,
                              void* d_out, int out_size)
{
    (void)in_sizes; (void)n_in; (void)out_size;
    const float* x    = (const float*)d_in[0];
    const float* Wih0 = (const float*)d_in[1];
    const float* Whh0 = (const float*)d_in[2];
    const float* bih0 = (const float*)d_in[3];
    const float* bhh0 = (const float*)d_in[4];
    const float* Wih1 = (const float*)d_in[5];
    const float* Whh1 = (const float*)d_in[6];
    const float* bih1 = (const float*)d_in[7];
    const float* bhh1 = (const float*)d_in[8];
    const float* Wih2 = (const float*)d_in[9];
    const float* Whh2 = (const float*)d_in[10];
    const float* bih2 = (const float*)d_in[11];
    const float* bhh2 = (const float*)d_in[12];
    float* out = (float*)d_out;

    float* tmp = nullptr;
    cudaGetSymbolAddress((void**)&tmp, g_tmp);
    __nv_bfloat16 *Ah = nullptr, *Al = nullptr, *Wh = nullptr, *Wl = nullptr;
    cudaGetSymbolAddress((void**)&Ah, g_Ah);
    cudaGetSymbolAddress((void**)&Al, g_Al);
    cudaGetSymbolAddress((void**)&Wh, g_Wh);
    cudaGetSymbolAddress((void**)&Wl, g_Wl);

    // Scan SMEM: (4*CW + RW)*SPAD + 9*RW*CWP floats
    const int smem0 = ((4 * 16 + 16) * SPAD + 9 * 16 * 18) * 4;   //  93952 B
    const int smem1 = ((4 * 32 + 16) * SPAD + 9 * 16 * 36) * 4;   // 170496 B
    const int smem2 = ((4 * 32 + 32) * SPAD + 9 * 32 * 36) * 4;   // 207872 B
    cudaFuncSetAttribute((const void*)scan_kernel<128, 16, 1>,
                         cudaFuncAttributeMaxDynamicSharedMemorySize, smem0);
    cudaFuncSetAttribute((const void*)scan_kernel<256, 32, 2>,
                         cudaFuncAttributeMaxDynamicSharedMemorySize, smem1);
    cudaFuncSetAttribute((const void*)scan_kernel<512, 32, 4>,
                         cudaFuncAttributeMaxDynamicSharedMemorySize, smem2);

    const int gsm = 1024 + 2 * 32768;
    cudaFuncSetAttribute((const void*)gemm_hmma_kernel<128>,
                         cudaFuncAttributeMaxDynamicSharedMemorySize, gsm);
    cudaFuncSetAttribute((const void*)gemm_hmma_kernel<256>,
                         cudaFuncAttributeMaxDynamicSharedMemorySize, gsm);

    dim3 ggrid(8, 1024);   // 128-col x 128-row tiles over [131072 x 1024]

    // ---- Layer 0: K=128, MB=128, 1024 steps
    {
        int n4a = RTOT * 128 / 4;
        convert_split_kernel<<<(n4a + 255) / 256, 256>>>(x, Ah, Al, n4a);
        int n4w = 1024 * 128 / 4;
        convert_split_kernel<<<(n4w + 255) / 256, 256>>>(Wih0, Wh, Wl, n4w);
        gemm_hmma_kernel<128><<<ggrid, 256, gsm>>>(bih0, bhh0);
        scan_kernel<128, 16, 1><<<128, 256, smem0>>>(Whh0, tmp, 1024);
    }
    // ---- Layer 1: K=256, MB=256, 512 steps
    {
        int n4a = RTOT * 256 / 4;
        convert_split_kernel<<<(n4a + 255) / 256, 256>>>(tmp, Ah, Al, n4a);
        int n4w = 1024 * 256 / 4;
        convert_split_kernel<<<(n4w + 255) / 256, 256>>>(Wih1, Wh, Wl, n4w);
        gemm_hmma_kernel<256><<<ggrid, 256, gsm>>>(bih1, bhh1);
        scan_kernel<256, 32, 2><<<128, 256, smem1>>>(Whh1, tmp, 512);
    }
    // ---- Layer 2: K=256, MB=512, 256 steps (writes final output)
    {
        int n4a = RTOT * 256 / 4;
        convert_split_kernel<<<(n4a + 255) / 256, 256>>>(tmp, Ah, Al, n4a);
        int n4w = 1024 * 256 / 4;
        convert_split_kernel<<<(n4w + 255) / 256, 256>>>(Wih2, Wh, Wl, n4w);
        gemm_hmma_kernel<256><<<ggrid, 256, gsm>>>(bih2, bhh2);
        scan_kernel<512, 32, 4><<<128, 256, smem2>>>(Whh2, out, 256);
    }
}